// round 9
// baseline (speedup 1.0000x reference)
#include <cuda_runtime.h>
#include <cstdint>

#define BSZ 4
#define LM  256
#define LE  512
#define HD  512
#define VOC 32000
#define HALF (VOC / 2)   // 16000 floats = 64 KB smem per scatter block

#define STAGES 3
#define TILEF  2304      // floats per A or B stage buffer (64*36 or 32*72)
#define GSMEM  (STAGES * 2 * TILEF * 4)   // 55296 B dynamic smem per GEMM block

// Scratch (device globals; no allocation allowed in kernel_launch)
__device__ float g_G[HD * HD];               // Wm @ We^T * scale    (1 MB)
__device__ float g_T[BSZ * LM * HD];         // M @ G                (2 MB)
__device__ float g_log[4][BSZ * LM * LE];    // logits K-split partials (8 MB)

// ---------------------------------------------------------------------------
// Zero the atomic accumulators (G and T). Tiny (3 MB).
// ---------------------------------------------------------------------------
__global__ __launch_bounds__(256) void k_zero(
    float4* __restrict__ a, long na4, float4* __restrict__ b, long nb4)
{
    long i = (long)blockIdx.x * blockDim.x + threadIdx.x;
    long s = (long)gridDim.x * blockDim.x;
    float4 z = make_float4(0.f, 0.f, 0.f, 0.f);
    for (long j = i; j < na4; j += s) a[j] = z;
    for (long j = i; j < nb4; j += s) b[j] = z;
}

// ---------------------------------------------------------------------------
// tf32 tensor-core GEMM core: 64x64 tile, 256 threads (4x2 warps of 16x32),
// BK=32, 3-stage cp.async pipeline, mma.sync.m16n8k8.tf32.
// TB=true:  C[m,n] (+)= alpha * sum_k A[m,k] * B[n,k]   (NT, both K-major)
// TB=false: C[m,n] (+)= alpha * sum_k A[m,k] * B[k,n]   (NN)
// ATOMIC=true: accumulate into C with atomicAdd (for K-split partial sums).
// ---------------------------------------------------------------------------
__device__ __forceinline__ void cp16(void* dst, const void* src)
{
    uint32_t d = (uint32_t)__cvta_generic_to_shared(dst);
    asm volatile("cp.async.cg.shared.global [%0], [%1], 16;\n"
                 :: "r"(d), "l"(src));
}
__device__ __forceinline__ void cp_commit()
{
    asm volatile("cp.async.commit_group;\n" ::: "memory");
}
__device__ __forceinline__ void cp_wait0()
{
    asm volatile("cp.async.wait_group 0;\n" ::: "memory");
}
__device__ __forceinline__ void cp_wait1()
{
    asm volatile("cp.async.wait_group 1;\n" ::: "memory");
}
__device__ __forceinline__ void mma_tf32(float* d, const uint32_t* a,
                                         const uint32_t* b)
{
    asm volatile(
        "mma.sync.aligned.m16n8k8.row.col.f32.tf32.tf32.f32 "
        "{%0,%1,%2,%3}, {%4,%5,%6,%7}, {%8,%9}, {%0,%1,%2,%3};\n"
        : "+f"(d[0]), "+f"(d[1]), "+f"(d[2]), "+f"(d[3])
        : "r"(a[0]), "r"(a[1]), "r"(a[2]), "r"(a[3]),
          "r"(b[0]), "r"(b[1]));
}

#define PA 36   // smem pitch, K-major tiles (banks 4*gid+tig: conflict-free)
#define PB 72   // smem pitch, NN B tile     (banks 8*tig+gid: conflict-free)

template <bool TB, bool ATOMIC>
__device__ __forceinline__ void gemm_core(
    const float* __restrict__ A, const float* __restrict__ B,
    float* __restrict__ C, int lda, int ldb, int ldc,
    int m0, int n0, int kOff, int kLen, float alpha, float* smem)
{
    float (*As)[TILEF] = reinterpret_cast<float(*)[TILEF]>(smem);
    float (*Bs)[TILEF] = reinterpret_cast<float(*)[TILEF]>(smem
                                                           + STAGES * TILEF);

    const int tid  = threadIdx.x;
    const int lane = tid & 31, w = tid >> 5;
    const int gid = lane >> 2, tig = lane & 3;
    const int wm = (w & 3) * 16, wn = (w >> 2) * 32;

    const int NK = kLen / 32;

    auto loadA = [&](int st, int kt) {
        int k0 = kOff + kt * 32;
#pragma unroll
        for (int i = 0; i < 2; i++) {
            int id = tid + i * 256;
            int row = id >> 3, cc = id & 7;
            cp16(&As[st][row * PA + cc * 4],
                 A + (long)(m0 + row) * lda + k0 + cc * 4);
        }
    };
    auto loadB = [&](int st, int kt) {
        int k0 = kOff + kt * 32;
        if (TB) {
#pragma unroll
            for (int i = 0; i < 2; i++) {
                int id = tid + i * 256;
                int row = id >> 3, cc = id & 7;
                cp16(&Bs[st][row * PA + cc * 4],
                     B + (long)(n0 + row) * ldb + k0 + cc * 4);
            }
        } else {
#pragma unroll
            for (int i = 0; i < 2; i++) {
                int id = tid + i * 256;
                int row = id >> 4, cc = id & 15;
                cp16(&Bs[st][row * PB + cc * 4],
                     B + (long)(k0 + row) * ldb + n0 + cc * 4);
            }
        }
    };

    float acc[4][4] = {};

    // prologue: 2 stages in flight
    loadA(0, 0); loadB(0, 0); cp_commit();
    if (NK > 1) { loadA(1, 1); loadB(1, 1); cp_commit(); }

    int buf = 0;        // stage being consumed this iter
    int ls  = 2;        // stage the next prefetch writes into
    for (int kt = 0; kt < NK; kt++) {
        if (kt < NK - 1) cp_wait1(); else cp_wait0();
        __syncthreads();
        if (kt + 2 < NK) {
            loadA(ls, kt + 2);
            loadB(ls, kt + 2);
            cp_commit();
            ls = (ls == STAGES - 1) ? 0 : ls + 1;
        }
#pragma unroll
        for (int ks = 0; ks < 4; ks++) {
            const int kk = ks * 8;
            uint32_t a[4];
            {
                int rb = wm + gid;
                a[0] = __float_as_uint(As[buf][(rb)     * PA + kk + tig]);
                a[1] = __float_as_uint(As[buf][(rb + 8) * PA + kk + tig]);
                a[2] = __float_as_uint(As[buf][(rb)     * PA + kk + tig + 4]);
                a[3] = __float_as_uint(As[buf][(rb + 8) * PA + kk + tig + 4]);
            }
            uint32_t b[4][2];
#pragma unroll
            for (int nj = 0; nj < 4; nj++) {
                int cb = wn + nj * 8 + gid;
                if (TB) {
                    b[nj][0] = __float_as_uint(Bs[buf][cb * PA + kk + tig]);
                    b[nj][1] = __float_as_uint(Bs[buf][cb * PA + kk + tig + 4]);
                } else {
                    b[nj][0] = __float_as_uint(Bs[buf][(kk + tig)     * PB + cb]);
                    b[nj][1] = __float_as_uint(Bs[buf][(kk + tig + 4) * PB + cb]);
                }
            }
#pragma unroll
            for (int nj = 0; nj < 4; nj++)
                mma_tf32(acc[nj], a, b[nj]);
        }
        buf = (buf == STAGES - 1) ? 0 : buf + 1;
    }

#pragma unroll
    for (int nj = 0; nj < 4; nj++) {
        int r0 = m0 + wm + gid;
        int c0 = n0 + wn + nj * 8 + 2 * tig;
        if (ATOMIC) {
            atomicAdd(&C[(long)r0 * ldc + c0],           acc[nj][0] * alpha);
            atomicAdd(&C[(long)r0 * ldc + c0 + 1],       acc[nj][1] * alpha);
            atomicAdd(&C[(long)(r0 + 8) * ldc + c0],     acc[nj][2] * alpha);
            atomicAdd(&C[(long)(r0 + 8) * ldc + c0 + 1], acc[nj][3] * alpha);
        } else {
            C[(long)r0 * ldc + c0]           = acc[nj][0] * alpha;
            C[(long)r0 * ldc + c0 + 1]       = acc[nj][1] * alpha;
            C[(long)(r0 + 8) * ldc + c0]     = acc[nj][2] * alpha;
            C[(long)(r0 + 8) * ldc + c0 + 1] = acc[nj][3] * alpha;
        }
    }
}

// ---------------------------------------------------------------------------
// G = Wm @ We^T * scale  (512x512, NT), K-split x4 with atomic accumulation.
// grid = (8, 8, 4) = 256 blocks.
// ---------------------------------------------------------------------------
__global__ __launch_bounds__(256) void k_G(
    const float* __restrict__ Wm, const float* __restrict__ We,
    float* __restrict__ G, float scale)
{
    extern __shared__ float smem[];
    gemm_core<true, true>(Wm, We, G, HD, HD, HD,
                          blockIdx.y * 64, blockIdx.x * 64,
                          blockIdx.z * 128, 128, scale, smem);
}

// ---------------------------------------------------------------------------
// T = M_flat @ G  (1024x512, NN), K-split x2 with atomic accumulation.
// grid = (8, 16, 2) = 256 blocks.
// ---------------------------------------------------------------------------
__global__ __launch_bounds__(256) void k_T(
    const float* __restrict__ M, const float* __restrict__ G,
    float* __restrict__ T)
{
    extern __shared__ float smem[];
    gemm_core<false, true>(M, G, T, HD, HD, HD,
                           blockIdx.y * 64, blockIdx.x * 64,
                           blockIdx.z * 256, 256, 1.f, smem);
}

// ---------------------------------------------------------------------------
// logits[b] = T[b] @ E[b]^T (NT), K-split x4 into 4 separate partial buffers.
// grid = (8, 4, 16): z = b*4 + h.
// ---------------------------------------------------------------------------
__global__ __launch_bounds__(256) void k_log(
    const float* __restrict__ T, const float* __restrict__ E,
    float* __restrict__ logs)
{
    extern __shared__ float smem[];
    int z = blockIdx.z;
    int b = z >> 2, h = z & 3;
    const float* A = T + (long)b * LM * HD;
    const float* B = E + (long)b * LE * HD;
    float* C = logs + (long)h * BSZ * LM * LE + (long)b * LM * LE;
    gemm_core<true, false>(A, B, C, HD, HD, LE,
                           blockIdx.y * 64, blockIdx.x * 64,
                           h * 128, 128, 1.f, smem);
}

// ---------------------------------------------------------------------------
// Block reduction for 512 threads (16 warps). red16 is a 16-float smem array.
// ---------------------------------------------------------------------------
__device__ __forceinline__ float bred512(float v, bool mx, float* red16,
                                         int lane, int w)
{
#pragma unroll
    for (int o = 16; o > 0; o >>= 1) {
        float u = __shfl_xor_sync(0xffffffffu, v, o);
        v = mx ? fmaxf(v, u) : v + u;
    }
    if (lane == 0) red16[w] = v;
    __syncthreads();
    float x = red16[lane & 15];
#pragma unroll
    for (int o = 8; o > 0; o >>= 1) {
        float u = __shfl_xor_sync(0xffffffffu, x, o);
        x = mx ? fmaxf(x, u) : x + u;
    }
    __syncthreads();   // red16 free for next use
    return x;          // identical in every thread
}

// ---------------------------------------------------------------------------
// Fused output kernel. grid = (2 vocab halves, 1024 rows), 512 threads,
// 64 KB dynamic smem (half an output row). Per block:
//   zero smem half-row; compute lambda inline; sum K-split logit partials;
//   dual softmax; scatter-add into smem; stream the half-row to GMEM (__stcs).
// No pre-zero pass and no global atomics: output is written exactly once.
// ---------------------------------------------------------------------------
__global__ __launch_bounds__(512) void k_scatter(
    const int* __restrict__ idx, const float* __restrict__ bq,
    const float* __restrict__ bc, const float* __restrict__ D,
    const float* __restrict__ Cq, const float* __restrict__ Cc,
    const float* __restrict__ Wl, const float* __restrict__ bl,
    const float* __restrict__ logs, float* __restrict__ out)
{
    extern __shared__ float vrow[];          // HALF floats (64 KB)
    __shared__ float red16[16];

    const int r = blockIdx.y;                // 0 .. BSZ*LM-1
    const int h = blockIdx.x;                // vocab half
    const int b = r >> 8;                    // r / LM
    const int t = threadIdx.x, lane = t & 31, w = t >> 5;

    // zero the smem half-row
    float4* v4 = (float4*)vrow;
    for (int i = t; i < HALF / 4; i += 512)
        v4[i] = make_float4(0.f, 0.f, 0.f, 0.f);

    // lambda (512 threads x 1 element each of the 3 concatenated chunks)
    const float* dr  = D  + (long)r * HD;
    const float* cqr = Cq + (long)r * HD;
    const float* ccr = Cc + (long)r * HD;
    float s = dr[t] * Wl[t] + cqr[t] * Wl[HD + t] + ccr[t] * Wl[2 * HD + t];
    s = bred512(s, false, red16, lane, w);
    float lam = 1.f / (1.f + __expf(-(s + bl[0])));

    // logits: one element per thread (LE == 512), sum of 4 K-split partials
    const long rl = (long)r * LE + t;
    const long str = (long)BSZ * LM * LE;
    float l = logs[rl] + logs[str + rl] + logs[2 * str + rl] + logs[3 * str + rl];
    float vq = l + bq[b * LE + t];
    float vc = l + bc[b * LE + t];

    float mq = bred512(vq, true, red16, lane, w);
    float mc = bred512(vc, true, red16, lane, w);
    float eq = __expf(vq - mq);
    float ec = __expf(vc - mc);
    float sq = bred512(eq, false, red16, lane, w);
    float sc = bred512(ec, false, red16, lane, w);

    float wgt = lam * eq / sq + (1.f - lam) * ec / sc;
    int ix = idx[b * LE + t] - h * HALF;
    if (ix >= 0 && ix < HALF)
        atomicAdd(&vrow[ix], wgt);
    __syncthreads();

    // stream the half-row out (write-once; no pre-zero needed)
    float4* orow4 = (float4*)(out + (long)r * VOC + (long)h * HALF);
    for (int i = t; i < HALF / 4; i += 512)
        __stcs(orow4 + i, v4[i]);
}

// ---------------------------------------------------------------------------
extern "C" void kernel_launch(void* const* d_in, const int* in_sizes, int n_in,
                              void* d_out, int out_size)
{
    const int*   inputs = (const int*)  d_in[0];
    const float* D      = (const float*)d_in[1];
    const float* Cq     = (const float*)d_in[2];
    const float* Cc     = (const float*)d_in[3];
    const float* Mi     = (const float*)d_in[4];
    const float* E      = (const float*)d_in[5];
    const float* bq     = (const float*)d_in[6];
    const float* bc     = (const float*)d_in[7];
    const float* Wl     = (const float*)d_in[8];
    const float* bl     = (const float*)d_in[9];
    const float* We     = (const float*)d_in[10];
    const float* Wm     = (const float*)d_in[11];
    float* out = (float*)d_out;

    float *gG, *gT, *gL;
    cudaGetSymbolAddress((void**)&gG, g_G);
    cudaGetSymbolAddress((void**)&gT, g_T);
    cudaGetSymbolAddress((void**)&gL, g_log);

    static bool init = false;
    if (!init) {
        cudaFuncSetAttribute(k_scatter,
                             cudaFuncAttributeMaxDynamicSharedMemorySize,
                             HALF * sizeof(float));
        cudaFuncSetAttribute(k_G,
                             cudaFuncAttributeMaxDynamicSharedMemorySize,
                             GSMEM);
        cudaFuncSetAttribute(k_T,
                             cudaFuncAttributeMaxDynamicSharedMemorySize,
                             GSMEM);
        cudaFuncSetAttribute(k_log,
                             cudaFuncAttributeMaxDynamicSharedMemorySize,
                             GSMEM);
        init = true;
    }

    const float scale = 0.044194173824159216f;  // 512^-0.5

    // zero atomic accumulators (G: 1 MB, T: 2 MB)
    k_zero<<<192, 256>>>((float4*)gG, HD * HD / 4,
                         (float4*)gT, (long)BSZ * LM * HD / 4);
    // G = Wm @ We^T * scale   (K-split x4, atomic epilogue, 256 blocks)
    k_G<<<dim3(8, 8, 4), 256, GSMEM>>>(Wm, We, gG, scale);
    // T = M_flat @ G          (K-split x2, atomic epilogue, 256 blocks)
    k_T<<<dim3(8, 16, 2), 256, GSMEM>>>(Mi, gG, gT);
    // logits partials         (K-split x4 into 4 buffers, 512 blocks)
    k_log<<<dim3(8, 4, 16), 256, GSMEM>>>(gT, E, gL);
    // fused lambda + softmax + scatter + streamed row write (2048 blocks)
    k_scatter<<<dim3(2, BSZ * LM), 512, HALF * sizeof(float)>>>(
        inputs, bq, bc, D, Cq, Cc, Wl, bl, gL, out);
}